// round 1
// baseline (speedup 1.0000x reference)
#include <cuda_runtime.h>

#define HID 10
#define EPW 3           // elements per warp (3*10 = 30 active lanes)
#define WPC 4           // warps per CTA
#define FULLMASK 0xffffffffu

__device__ __forceinline__ float sigm(float x) {
    float e = __expf(-x);
    return __fdividef(1.0f, 1.0f + e);
}
__device__ __forceinline__ float tanh_(float x) {
    float e = __expf(2.0f * x);
    return __fdividef(e - 1.0f, e + 1.0f);
}

__global__ void __launch_bounds__(WPC * 32)
lstm2_kernel(const float* __restrict__ x,
             const float* __restrict__ W_ih1, const float* __restrict__ W_hh1,
             const float* __restrict__ b_ih1, const float* __restrict__ b_hh1,
             const float* __restrict__ W_ih2, const float* __restrict__ W_hh2,
             const float* __restrict__ b_ih2, const float* __restrict__ b_hh2,
             const float* __restrict__ W_lin, const float* __restrict__ b_lin,
             float* __restrict__ out, int T, int Ttot, int B)
{
    const int lane = threadIdx.x & 31;
    const int warp = threadIdx.x >> 5;
    const int le   = lane / HID;          // local element 0..2 (3 = idle lanes 30,31)
    const int j    = lane - le * HID;     // hidden index 0..9
    const int base = le * HID;            // first lane of this element's group
    const int e    = (blockIdx.x * WPC + warp) * EPW + le;
    const bool active = (le < EPW) && (e < B);

    // ---- weights in registers (per-thread rows: gate g -> row g*HID + j) ----
    float Wih1r[4], bias1[4], bias2[4];
    float Whh1[4][HID], Wih2[4][HID], Whh2[4][HID];
    float Wlin[HID], blin;

    #pragma unroll
    for (int g = 0; g < 4; g++) {
        int row = g * HID + j;            // valid address for every lane
        Wih1r[g] = __ldg(&W_ih1[row]);
        bias1[g] = __ldg(&b_ih1[row]) + __ldg(&b_hh1[row]);
        bias2[g] = __ldg(&b_ih2[row]) + __ldg(&b_hh2[row]);
        #pragma unroll
        for (int k = 0; k < HID; k++) {
            Whh1[g][k] = __ldg(&W_hh1[row * HID + k]);
            Wih2[g][k] = __ldg(&W_ih2[row * HID + k]);
            Whh2[g][k] = __ldg(&W_hh2[row * HID + k]);
        }
    }
    #pragma unroll
    for (int k = 0; k < HID; k++) Wlin[k] = __ldg(&W_lin[k]);
    blin = __ldg(&b_lin[0]);

    // ---- recurrent state ----
    float h1 = 0.f, c1 = 0.f, h2 = 0.f, c2 = 0.f;
    float h1v[HID];                        // gathered h1 (post previous step)
    #pragma unroll
    for (int k = 0; k < HID; k++) h1v[k] = 0.f;

    const int xb = (active ? e : 0) * T;
    const int ob = (active ? e : 0) * Ttot;

    // ---- x chunk prefetch: 8 timesteps per chunk, double buffered ----
    const int CH = 8;
    float xcur = 0.f, xnxt = 0.f;
    if (active && j < CH && j < T)       xcur = __ldg(&x[xb + j]);
    if (active && j < CH && CH + j < T)  xnxt = __ldg(&x[xb + CH + j]);

    for (int t = 0; t < Ttot; t++) {
        // gather h2 (state after step t-1)
        float h2v[HID];
        #pragma unroll
        for (int k = 0; k < HID; k++)
            h2v[k] = __shfl_sync(FULLMASK, h2, base + k);

        // output of step t-1 (also the autoregressive input for t >= T)
        float y = blin;
        #pragma unroll
        for (int k = 0; k < HID; k++) y = fmaf(h2v[k], Wlin[k], y);
        if (t > 0 && active && j == 0) out[ob + (t - 1)] = y;

        float xt;
        if (t < T) xt = __shfl_sync(FULLMASK, xcur, base + (t & (CH - 1)));
        else       xt = y;

        // ---- layer 1 cell (uses h1v = h1 after step t-1) ----
        float a0 = fmaf(Wih1r[0], xt, bias1[0]);
        float a1 = fmaf(Wih1r[1], xt, bias1[1]);
        float a2 = fmaf(Wih1r[2], xt, bias1[2]);
        float a3 = fmaf(Wih1r[3], xt, bias1[3]);
        #pragma unroll
        for (int k = 0; k < HID; k++) {
            float h = h1v[k];
            a0 = fmaf(Whh1[0][k], h, a0);
            a1 = fmaf(Whh1[1][k], h, a1);
            a2 = fmaf(Whh1[2][k], h, a2);
            a3 = fmaf(Whh1[3][k], h, a3);
        }
        float ig = sigm(a0), fg = sigm(a1), gg = tanh_(a2), og = sigm(a3);
        c1 = fmaf(fg, c1, ig * gg);
        h1 = og * tanh_(c1);

        // gather new h1 (used by layer-2 now AND layer-1 next step)
        #pragma unroll
        for (int k = 0; k < HID; k++)
            h1v[k] = __shfl_sync(FULLMASK, h1, base + k);

        // ---- layer 2 cell (input = new h1, recurrent = old h2) ----
        float g0 = bias2[0], g1 = bias2[1], g2 = bias2[2], g3 = bias2[3];
        #pragma unroll
        for (int k = 0; k < HID; k++) {
            float ha = h1v[k];
            g0 = fmaf(Wih2[0][k], ha, g0);
            g1 = fmaf(Wih2[1][k], ha, g1);
            g2 = fmaf(Wih2[2][k], ha, g2);
            g3 = fmaf(Wih2[3][k], ha, g3);
        }
        #pragma unroll
        for (int k = 0; k < HID; k++) {
            float hb = h2v[k];
            g0 = fmaf(Whh2[0][k], hb, g0);
            g1 = fmaf(Whh2[1][k], hb, g1);
            g2 = fmaf(Whh2[2][k], hb, g2);
            g3 = fmaf(Whh2[3][k], hb, g3);
        }
        float i2 = sigm(g0), f2 = sigm(g1), t2 = tanh_(g2), o2 = sigm(g3);
        c2 = fmaf(f2, c2, i2 * t2);
        h2 = o2 * tanh_(c2);

        // rotate / refill x chunk (prefetch 1 chunk ahead; latency fully hidden)
        if (t < T && (t & (CH - 1)) == (CH - 1)) {
            xcur = xnxt;
            int nt = t + 1 + CH;
            if (active && j < CH && nt + j < T) xnxt = __ldg(&x[xb + nt + j]);
        }
    }

    // final output y[Ttot-1]
    {
        float y = blin;
        #pragma unroll
        for (int k = 0; k < HID; k++) {
            float hk = __shfl_sync(FULLMASK, h2, base + k);
            y = fmaf(hk, Wlin[k], y);
        }
        if (active && j == 0) out[ob + (Ttot - 1)] = y;
    }
}

extern "C" void kernel_launch(void* const* d_in, const int* in_sizes, int n_in,
                              void* d_out, int out_size) {
    const float* x     = (const float*)d_in[0];
    const float* W_ih1 = (const float*)d_in[1];
    const float* W_hh1 = (const float*)d_in[2];
    const float* b_ih1 = (const float*)d_in[3];
    const float* b_hh1 = (const float*)d_in[4];
    const float* W_ih2 = (const float*)d_in[5];
    const float* W_hh2 = (const float*)d_in[6];
    const float* b_ih2 = (const float*)d_in[7];
    const float* b_hh2 = (const float*)d_in[8];
    const float* W_lin = (const float*)d_in[9];
    const float* b_lin = (const float*)d_in[10];
    float* out = (float*)d_out;

    const int B    = 2048;               // fixed problem shape
    const int T    = in_sizes[0] / B;    // 1024
    const int Ttot = out_size / B;       // T + future = 1088

    int warps  = (B + EPW - 1) / EPW;        // 683
    int blocks = (warps + WPC - 1) / WPC;    // 171

    lstm2_kernel<<<blocks, WPC * 32>>>(x, W_ih1, W_hh1, b_ih1, b_hh1,
                                       W_ih2, W_hh2, b_ih2, b_hh2,
                                       W_lin, b_lin, out, T, Ttot, B);
}

// round 4
// speedup vs baseline: 1.2956x; 1.2956x over previous
#include <cuda_runtime.h>

#define HID 10
#define EPW 3           // elements per warp (3*10 = 30 active lanes)
#define WPC 4           // warps per CTA
#define FULLMASK 0xffffffffu

typedef unsigned long long u64;

__device__ __forceinline__ float tanha(float x) {
    float r; asm("tanh.approx.f32 %0, %1;" : "=f"(r) : "f"(x)); return r;
}
__device__ __forceinline__ float sigm(float x) {
    return fmaf(tanha(0.5f * x), 0.5f, 0.5f);
}
__device__ __forceinline__ u64 pk(float lo, float hi) {
    u64 r; asm("mov.b64 %0, {%1, %2};" : "=l"(r) : "f"(lo), "f"(hi)); return r;
}
__device__ __forceinline__ void upk(float& lo, float& hi, u64 v) {
    asm("mov.b64 {%0, %1}, %2;" : "=f"(lo), "=f"(hi) : "l"(v));
}
__device__ __forceinline__ u64 fma2(u64 a, u64 b, u64 c) {
    u64 d; asm("fma.rn.f32x2 %0, %1, %2, %3;" : "=l"(d) : "l"(a), "l"(b), "l"(c)); return d;
}

__global__ void __launch_bounds__(WPC * 32)
lstm2_kernel(const float* __restrict__ x,
             const float* __restrict__ W_ih1, const float* __restrict__ W_hh1,
             const float* __restrict__ b_ih1, const float* __restrict__ b_hh1,
             const float* __restrict__ W_ih2, const float* __restrict__ W_hh2,
             const float* __restrict__ b_ih2, const float* __restrict__ b_hh2,
             const float* __restrict__ W_lin, const float* __restrict__ b_lin,
             float* __restrict__ out, int T, int Ttot, int B)
{
    const int lane = threadIdx.x & 31;
    const int warp = threadIdx.x >> 5;
    const int le   = lane / HID;          // local element 0..2 (3 = tail lanes)
    const int j    = lane - le * HID;     // hidden index 0..9
    const int base = le * HID;
    const int e    = (blockIdx.x * WPC + warp) * EPW + le;
    const bool active = (le < EPW) && (e < B);

    // ---- packed weights in registers ----
    // Gate pairing: A = (i,f) = rows (j, HID+j); B = (g,o) = rows (2*HID+j, 3*HID+j)
    u64 Wih1A, Wih1B, b1A, b1B, b2A, b2B;
    u64 Whh1A[HID], Whh1B[HID];
    u64 Wih2A[HID], Wih2B[HID];
    u64 Whh2A[HID], Whh2B[HID];
    float Wlin[HID], blin;

    {
        int r0 = j, r1 = HID + j, r2 = 2 * HID + j, r3 = 3 * HID + j;
        Wih1A = pk(__ldg(&W_ih1[r0]), __ldg(&W_ih1[r1]));
        Wih1B = pk(__ldg(&W_ih1[r2]), __ldg(&W_ih1[r3]));
        b1A = pk(__ldg(&b_ih1[r0]) + __ldg(&b_hh1[r0]), __ldg(&b_ih1[r1]) + __ldg(&b_hh1[r1]));
        b1B = pk(__ldg(&b_ih1[r2]) + __ldg(&b_hh1[r2]), __ldg(&b_ih1[r3]) + __ldg(&b_hh1[r3]));
        b2A = pk(__ldg(&b_ih2[r0]) + __ldg(&b_hh2[r0]), __ldg(&b_ih2[r1]) + __ldg(&b_hh2[r1]));
        b2B = pk(__ldg(&b_ih2[r2]) + __ldg(&b_hh2[r2]), __ldg(&b_ih2[r3]) + __ldg(&b_hh2[r3]));
        #pragma unroll
        for (int k = 0; k < HID; k++) {
            Whh1A[k] = pk(__ldg(&W_hh1[r0 * HID + k]), __ldg(&W_hh1[r1 * HID + k]));
            Whh1B[k] = pk(__ldg(&W_hh1[r2 * HID + k]), __ldg(&W_hh1[r3 * HID + k]));
            Wih2A[k] = pk(__ldg(&W_ih2[r0 * HID + k]), __ldg(&W_ih2[r1 * HID + k]));
            Wih2B[k] = pk(__ldg(&W_ih2[r2 * HID + k]), __ldg(&W_ih2[r3 * HID + k]));
            Whh2A[k] = pk(__ldg(&W_hh2[r0 * HID + k]), __ldg(&W_hh2[r1 * HID + k]));
            Whh2B[k] = pk(__ldg(&W_hh2[r2 * HID + k]), __ldg(&W_hh2[r3 * HID + k]));
        }
        #pragma unroll
        for (int k = 0; k < HID; k++) Wlin[k] = __ldg(&W_lin[k]);
        blin = __ldg(&b_lin[0]);
    }

    // ---- recurrent state ----
    float h1 = 0.f, c1 = 0.f, h2 = 0.f, c2 = 0.f;
    u64 h1p[HID];                      // packed (h1[k], h1[k]) from previous step
    #pragma unroll
    for (int k = 0; k < HID; k++) h1p[k] = 0ull;

    const int xb = (active ? e : 0) * T;
    const int ob = (active ? e : 0) * Ttot;

    // ---- x chunk prefetch: 8 timesteps per chunk, double buffered ----
    const int CH = 8;
    float xcur = 0.f, xnxt = 0.f;
    if (active && j < CH && j < T)       xcur = __ldg(&x[xb + j]);
    if (active && j < CH && CH + j < T)  xnxt = __ldg(&x[xb + CH + j]);

    for (int t = 0; t < Ttot; t++) {
        // gather h2 (state after step t-1), scalar + packed
        float h2v[HID]; u64 h2p[HID];
        #pragma unroll
        for (int k = 0; k < HID; k++) {
            h2v[k] = __shfl_sync(FULLMASK, h2, base + k);
            h2p[k] = pk(h2v[k], h2v[k]);
        }

        // ---- EARLY: layer-2 recurrent half (independent of layer-1 chain) ----
        u64 gA = b2A, gB = b2B;
        #pragma unroll
        for (int k = 0; k < HID; k++) {
            gA = fma2(Whh2A[k], h2p[k], gA);
            gB = fma2(Whh2B[k], h2p[k], gB);
        }

        // output of step t-1 (also autoregressive input for t >= T)
        float y = blin;
        #pragma unroll
        for (int k = 0; k < HID; k++) y = fmaf(h2v[k], Wlin[k], y);
        if (t > 0 && active && j == 0) out[ob + (t - 1)] = y;

        float xt;
        if (t < T) xt = __shfl_sync(FULLMASK, xcur, base + (t & (CH - 1)));
        else       xt = y;

        // ---- layer 1 cell ----
        u64 xx = pk(xt, xt);
        u64 aA = fma2(Wih1A, xx, b1A);
        u64 aB = fma2(Wih1B, xx, b1B);
        #pragma unroll
        for (int k = 0; k < HID; k++) {
            aA = fma2(Whh1A[k], h1p[k], aA);
            aB = fma2(Whh1B[k], h1p[k], aB);
        }
        float a0, a1, a2, a3;
        upk(a0, a1, aA); upk(a2, a3, aB);
        float ig = sigm(a0), fg = sigm(a1), gg = tanha(a2), og = sigm(a3);
        c1 = fmaf(fg, c1, ig * gg);
        h1 = og * tanha(c1);

        // gather new h1 (packed; reused by layer-2 now AND layer-1 next step)
        #pragma unroll
        for (int k = 0; k < HID; k++) {
            float v = __shfl_sync(FULLMASK, h1, base + k);
            h1p[k] = pk(v, v);
        }

        // ---- layer 2 cell: input half ----
        #pragma unroll
        for (int k = 0; k < HID; k++) {
            gA = fma2(Wih2A[k], h1p[k], gA);
            gB = fma2(Wih2B[k], h1p[k], gB);
        }
        float g0, g1, g2, g3;
        upk(g0, g1, gA); upk(g2, g3, gB);
        float i2 = sigm(g0), f2 = sigm(g1), t2 = tanha(g2), o2 = sigm(g3);
        c2 = fmaf(f2, c2, i2 * t2);
        h2 = o2 * tanha(c2);

        // rotate / refill x chunk
        if (t < T && (t & (CH - 1)) == (CH - 1)) {
            xcur = xnxt;
            int nt = t + 1 + CH;
            if (active && j < CH && nt + j < T) xnxt = __ldg(&x[xb + nt + j]);
        }
    }

    // final output y[Ttot-1]
    {
        float y = blin;
        #pragma unroll
        for (int k = 0; k < HID; k++) {
            float hk = __shfl_sync(FULLMASK, h2, base + k);
            y = fmaf(hk, Wlin[k], y);
        }
        if (active && j == 0) out[ob + (Ttot - 1)] = y;
    }
}

extern "C" void kernel_launch(void* const* d_in, const int* in_sizes, int n_in,
                              void* d_out, int out_size) {
    const float* x     = (const float*)d_in[0];
    const float* W_ih1 = (const float*)d_in[1];
    const float* W_hh1 = (const float*)d_in[2];
    const float* b_ih1 = (const float*)d_in[3];
    const float* b_hh1 = (const float*)d_in[4];
    const float* W_ih2 = (const float*)d_in[5];
    const float* W_hh2 = (const float*)d_in[6];
    const float* b_ih2 = (const float*)d_in[7];
    const float* b_hh2 = (const float*)d_in[8];
    const float* W_lin = (const float*)d_in[9];
    const float* b_lin = (const float*)d_in[10];
    float* out = (float*)d_out;

    const int B    = 2048;
    const int T    = in_sizes[0] / B;    // 1024
    const int Ttot = out_size / B;       // 1088

    int warps  = (B + EPW - 1) / EPW;        // 683
    int blocks = (warps + WPC - 1) / WPC;    // 171

    lstm2_kernel<<<blocks, WPC * 32>>>(x, W_ih1, W_hh1, b_ih1, b_hh1,
                                       W_ih2, W_hh2, b_ih2, b_hh2,
                                       W_lin, b_lin, out, T, Ttot, B);
}

// round 5
// speedup vs baseline: 1.3533x; 1.0446x over previous
#include <cuda_runtime.h>

#define HID 10
#define EPW 3           // elements per warp (3*10 = 30 active lanes)
#define WPC 4           // warps per CTA
#define FULLMASK 0xffffffffu

typedef unsigned long long u64;

__device__ __forceinline__ float tanha(float x) {
    float r; asm("tanh.approx.f32 %0, %1;" : "=f"(r) : "f"(x)); return r;
}
// input already pre-scaled by 0.5 via folded weights
__device__ __forceinline__ float sigm_pre(float xh) {
    return fmaf(tanha(xh), 0.5f, 0.5f);
}
__device__ __forceinline__ u64 pk(float lo, float hi) {
    u64 r; asm("mov.b64 %0, {%1, %2};" : "=l"(r) : "f"(lo), "f"(hi)); return r;
}
__device__ __forceinline__ void upk(float& lo, float& hi, u64 v) {
    asm("mov.b64 {%0, %1}, %2;" : "=f"(lo), "=f"(hi) : "l"(v));
}
__device__ __forceinline__ u64 fma2(u64 a, u64 b, u64 c) {
    u64 d; asm("fma.rn.f32x2 %0, %1, %2, %3;" : "=l"(d) : "l"(a), "l"(b), "l"(c)); return d;
}
__device__ __forceinline__ u64 add2(u64 a, u64 b) {
    u64 d; asm("add.rn.f32x2 %0, %1, %2;" : "=l"(d) : "l"(a), "l"(b)); return d;
}

__global__ void __launch_bounds__(WPC * 32)
lstm2_kernel(const float* __restrict__ x,
             const float* __restrict__ W_ih1, const float* __restrict__ W_hh1,
             const float* __restrict__ b_ih1, const float* __restrict__ b_hh1,
             const float* __restrict__ W_ih2, const float* __restrict__ W_hh2,
             const float* __restrict__ b_ih2, const float* __restrict__ b_hh2,
             const float* __restrict__ W_lin, const float* __restrict__ b_lin,
             float* __restrict__ out, int T, int Ttot, int B)
{
    const int lane = threadIdx.x & 31;
    const int warp = threadIdx.x >> 5;
    const int le   = lane / HID;
    const int j    = lane - le * HID;
    const int base = le * HID;
    const int e    = (blockIdx.x * WPC + warp) * EPW + le;
    const bool active = (le < EPW) && (e < B);

    // ---- packed weights in registers ----
    // A = (i,f): both sigmoid gates -> fold 0.5 into weights+bias.
    // B = (g,o): g=tanh (unscaled), o=sigmoid (fold 0.5).
    u64 Wih1A, Wih1B, b1A, b1B, b2A, b2B;
    u64 Whh1A[HID], Whh1B[HID];
    u64 Wih2A[HID], Wih2B[HID];
    u64 Whh2A[HID], Whh2B[HID];
    float Wlin[HID], blin;

    {
        int r0 = j, r1 = HID + j, r2 = 2 * HID + j, r3 = 3 * HID + j;
        Wih1A = pk(0.5f * __ldg(&W_ih1[r0]), 0.5f * __ldg(&W_ih1[r1]));
        Wih1B = pk(__ldg(&W_ih1[r2]), 0.5f * __ldg(&W_ih1[r3]));
        b1A = pk(0.5f * (__ldg(&b_ih1[r0]) + __ldg(&b_hh1[r0])),
                 0.5f * (__ldg(&b_ih1[r1]) + __ldg(&b_hh1[r1])));
        b1B = pk(        __ldg(&b_ih1[r2]) + __ldg(&b_hh1[r2]),
                 0.5f * (__ldg(&b_ih1[r3]) + __ldg(&b_hh1[r3])));
        b2A = pk(0.5f * (__ldg(&b_ih2[r0]) + __ldg(&b_hh2[r0])),
                 0.5f * (__ldg(&b_ih2[r1]) + __ldg(&b_hh2[r1])));
        b2B = pk(        __ldg(&b_ih2[r2]) + __ldg(&b_hh2[r2]),
                 0.5f * (__ldg(&b_ih2[r3]) + __ldg(&b_hh2[r3])));
        #pragma unroll
        for (int k = 0; k < HID; k++) {
            Whh1A[k] = pk(0.5f * __ldg(&W_hh1[r0 * HID + k]), 0.5f * __ldg(&W_hh1[r1 * HID + k]));
            Whh1B[k] = pk(       __ldg(&W_hh1[r2 * HID + k]), 0.5f * __ldg(&W_hh1[r3 * HID + k]));
            Wih2A[k] = pk(0.5f * __ldg(&W_ih2[r0 * HID + k]), 0.5f * __ldg(&W_ih2[r1 * HID + k]));
            Wih2B[k] = pk(       __ldg(&W_ih2[r2 * HID + k]), 0.5f * __ldg(&W_ih2[r3 * HID + k]));
            Whh2A[k] = pk(0.5f * __ldg(&W_hh2[r0 * HID + k]), 0.5f * __ldg(&W_hh2[r1 * HID + k]));
            Whh2B[k] = pk(       __ldg(&W_hh2[r2 * HID + k]), 0.5f * __ldg(&W_hh2[r3 * HID + k]));
        }
        #pragma unroll
        for (int k = 0; k < HID; k++) Wlin[k] = __ldg(&W_lin[k]);
        blin = __ldg(&b_lin[0]);
    }

    // ---- recurrent state ----
    float h1 = 0.f, c1 = 0.f, h2 = 0.f, c2 = 0.f;
    u64 h1p[HID];
    #pragma unroll
    for (int k = 0; k < HID; k++) h1p[k] = 0ull;
    const u64 Z = 0ull;

    const int xb = (active ? e : 0) * T;
    const int ob = (active ? e : 0) * Ttot;

    const int CH = 8;
    float xcur = 0.f, xnxt = 0.f;
    if (active && j < CH && j < T)       xcur = __ldg(&x[xb + j]);
    if (active && j < CH && CH + j < T)  xnxt = __ldg(&x[xb + CH + j]);

    for (int t = 0; t < Ttot; t++) {
        // gather h2 (state after step t-1)
        float h2v[HID]; u64 h2p[HID];
        #pragma unroll
        for (int k = 0; k < HID; k++) {
            h2v[k] = __shfl_sync(FULLMASK, h2, base + k);
            h2p[k] = pk(h2v[k], h2v[k]);
        }

        // ---- EARLY: layer-2 recurrent half (even/odd split chains) ----
        u64 gA0 = fma2(Whh2A[0], h2p[0], b2A);
        u64 gA1 = fma2(Whh2A[1], h2p[1], Z);
        u64 gB0 = fma2(Whh2B[0], h2p[0], b2B);
        u64 gB1 = fma2(Whh2B[1], h2p[1], Z);
        #pragma unroll
        for (int k = 2; k < HID; k += 2) {
            gA0 = fma2(Whh2A[k],     h2p[k],     gA0);
            gA1 = fma2(Whh2A[k + 1], h2p[k + 1], gA1);
            gB0 = fma2(Whh2B[k],     h2p[k],     gB0);
            gB1 = fma2(Whh2B[k + 1], h2p[k + 1], gB1);
        }

        // output of step t-1 (split dot)
        float y0 = fmaf(h2v[0], Wlin[0], blin);
        float y1 = h2v[1] * Wlin[1];
        #pragma unroll
        for (int k = 2; k < HID; k += 2) {
            y0 = fmaf(h2v[k],     Wlin[k],     y0);
            y1 = fmaf(h2v[k + 1], Wlin[k + 1], y1);
        }
        float y = y0 + y1;
        if (t > 0 && active && j == 0) out[ob + (t - 1)] = y;

        float xt;
        if (t < T) xt = __shfl_sync(FULLMASK, xcur, base + (t & (CH - 1)));
        else       xt = y;

        // ---- layer 1 cell: chain0 = x-term + even k, chain1 = odd k ----
        u64 xx = pk(xt, xt);
        u64 aA0 = fma2(Wih1A, xx, b1A);
        u64 aA1 = fma2(Whh1A[1], h1p[1], Z);
        u64 aB0 = fma2(Wih1B, xx, b1B);
        u64 aB1 = fma2(Whh1B[1], h1p[1], Z);
        aA0 = fma2(Whh1A[0], h1p[0], aA0);
        aB0 = fma2(Whh1B[0], h1p[0], aB0);
        #pragma unroll
        for (int k = 2; k < HID; k += 2) {
            aA0 = fma2(Whh1A[k],     h1p[k],     aA0);
            aA1 = fma2(Whh1A[k + 1], h1p[k + 1], aA1);
            aB0 = fma2(Whh1B[k],     h1p[k],     aB0);
            aB1 = fma2(Whh1B[k + 1], h1p[k + 1], aB1);
        }
        u64 aA = add2(aA0, aA1);
        u64 aB = add2(aB0, aB1);

        float a0, a1, a2, a3;
        upk(a0, a1, aA); upk(a2, a3, aB);
        float ig = sigm_pre(a0), fg = sigm_pre(a1);
        float gg = tanha(a2),    og = sigm_pre(a3);
        c1 = fmaf(fg, c1, ig * gg);
        h1 = og * tanha(c1);

        // gather new h1
        #pragma unroll
        for (int k = 0; k < HID; k++) {
            float v = __shfl_sync(FULLMASK, h1, base + k);
            h1p[k] = pk(v, v);
        }

        // ---- layer 2 input half (even/odd split chains) ----
        u64 gA2 = fma2(Wih2A[0], h1p[0], Z);
        u64 gA3 = fma2(Wih2A[1], h1p[1], Z);
        u64 gB2 = fma2(Wih2B[0], h1p[0], Z);
        u64 gB3 = fma2(Wih2B[1], h1p[1], Z);
        #pragma unroll
        for (int k = 2; k < HID; k += 2) {
            gA2 = fma2(Wih2A[k],     h1p[k],     gA2);
            gA3 = fma2(Wih2A[k + 1], h1p[k + 1], gA3);
            gB2 = fma2(Wih2B[k],     h1p[k],     gB2);
            gB3 = fma2(Wih2B[k + 1], h1p[k + 1], gB3);
        }
        u64 gA = add2(add2(gA0, gA1), add2(gA2, gA3));
        u64 gB = add2(add2(gB0, gB1), add2(gB2, gB3));

        float g0, g1, g2, g3;
        upk(g0, g1, gA); upk(g2, g3, gB);
        float i2 = sigm_pre(g0), f2 = sigm_pre(g1);
        float t2 = tanha(g2),    o2 = sigm_pre(g3);
        c2 = fmaf(f2, c2, i2 * t2);
        h2 = o2 * tanha(c2);

        // rotate / refill x chunk
        if (t < T && (t & (CH - 1)) == (CH - 1)) {
            xcur = xnxt;
            int nt = t + 1 + CH;
            if (active && j < CH && nt + j < T) xnxt = __ldg(&x[xb + nt + j]);
        }
    }

    // final output y[Ttot-1]
    {
        float y = blin;
        #pragma unroll
        for (int k = 0; k < HID; k++) {
            float hk = __shfl_sync(FULLMASK, h2, base + k);
            y = fmaf(hk, Wlin[k], y);
        }
        if (active && j == 0) out[ob + (Ttot - 1)] = y;
    }
}

extern "C" void kernel_launch(void* const* d_in, const int* in_sizes, int n_in,
                              void* d_out, int out_size) {
    const float* x     = (const float*)d_in[0];
    const float* W_ih1 = (const float*)d_in[1];
    const float* W_hh1 = (const float*)d_in[2];
    const float* b_ih1 = (const float*)d_in[3];
    const float* b_hh1 = (const float*)d_in[4];
    const float* W_ih2 = (const float*)d_in[5];
    const float* W_hh2 = (const float*)d_in[6];
    const float* b_ih2 = (const float*)d_in[7];
    const float* b_hh2 = (const float*)d_in[8];
    const float* W_lin = (const float*)d_in[9];
    const float* b_lin = (const float*)d_in[10];
    float* out = (float*)d_out;

    const int B    = 2048;
    const int T    = in_sizes[0] / B;    // 1024
    const int Ttot = out_size / B;       // 1088

    int warps  = (B + EPW - 1) / EPW;        // 683
    int blocks = (warps + WPC - 1) / WPC;    // 171

    lstm2_kernel<<<blocks, WPC * 32>>>(x, W_ih1, W_hh1, b_ih1, b_hh1,
                                       W_ih2, W_hh2, b_ih2, b_hh2,
                                       W_lin, b_lin, out, T, Ttot, B);
}